// round 8
// baseline (speedup 1.0000x reference)
#include <cuda_runtime.h>
#include <math.h>

#define BATCH 2
#define LDIM 3600
#define SDIM 3600
#define DDIM 256
#define LS 12960000
#define NP1 3601
#define NGROUPS 25
#define CGROUPS 16
#define MU_CONST (1.0f/7200.0f)
#define INV_SCALE 1.52587890625e-4f  // 1/(256*256*0.1)

static __device__ float    d_E[BATCH * LS];
static __device__ float    d_rinv[BATCH * LDIM];
static __device__ float    d_cinv[BATCH * SDIM];
static __device__ float    d_colpart[BATCH * CGROUPS * SDIM];
static __device__ unsigned d_rowmaxb[BATCH * LDIM];
static __device__ unsigned d_colmaxb[BATCH * SDIM];
static __device__ float    d_wu[BATCH * NP1];
static __device__ float    d_wv[BATCH * NP1];
static __device__ float    d_svpart[BATCH * NGROUPS * NP1];

__device__ __forceinline__ float warpSum(float v) {
#pragma unroll
    for (int o = 16; o > 0; o >>= 1) v += __shfl_down_sync(0xffffffffu, v, o);
    return v;
}
__device__ __forceinline__ float warpMax(float v) {
#pragma unroll
    for (int o = 16; o > 0; o >>= 1) v = fmaxf(v, __shfl_down_sync(0xffffffffu, v, o));
    return v;
}
// result valid in thread 0
__device__ __forceinline__ float blockSum256(float v, float* red) {
    int lane = threadIdx.x & 31, w = threadIdx.x >> 5;
    v = warpSum(v);
    if (lane == 0) red[w] = v;
    __syncthreads();
    float t = (threadIdx.x < 8) ? red[threadIdx.x] : 0.0f;
    if (w == 0) t = warpSum(t);
    return t;
}
// canonical cm expression; __fmul_rn blocks FMA contraction so every kernel
// recomputes bit-identical values for the ==max comparisons.
__device__ __forceinline__ float cm_val(float e, float ri, float cj) {
    return __fmul_rn(__fmul_rn(__fmul_rn(e, e), ri), cj);
}

// ---- K1: fp32 SGEMM (128x128x16) + exp epilogue -> d_E ----
__global__ void __launch_bounds__(256, 2)
gemm_exp_kernel(const float* __restrict__ Q, const float* __restrict__ R) {
    const int b = blockIdx.z;
    const int row0 = blockIdx.y * 128, col0 = blockIdx.x * 128;
    __shared__ float As[16][132];
    __shared__ float Bs[16][132];
    const int tid = threadIdx.x, tx = tid & 15, ty = tid >> 4;
    float acc[8][8];
#pragma unroll
    for (int i = 0; i < 8; i++)
#pragma unroll
        for (int j = 0; j < 8; j++) acc[i][j] = 0.0f;

    const float* Qb = Q + (long)b * LDIM * DDIM;
    const float* Rb = R + (long)b * SDIM * DDIM;

    for (int kt = 0; kt < DDIM; kt += 16) {
#pragma unroll
        for (int l = 0; l < 2; l++) {
            int f = tid + l * 256;
            int r = f >> 2, c4 = (f & 3) << 2;
            float4 va = make_float4(0.f, 0.f, 0.f, 0.f);
            int ga = row0 + r;
            if (ga < LDIM) va = *(const float4*)(Qb + (long)ga * DDIM + kt + c4);
            As[c4 + 0][r] = va.x; As[c4 + 1][r] = va.y;
            As[c4 + 2][r] = va.z; As[c4 + 3][r] = va.w;
            float4 vb = make_float4(0.f, 0.f, 0.f, 0.f);
            int gb = col0 + r;
            if (gb < SDIM) vb = *(const float4*)(Rb + (long)gb * DDIM + kt + c4);
            Bs[c4 + 0][r] = vb.x; Bs[c4 + 1][r] = vb.y;
            Bs[c4 + 2][r] = vb.z; Bs[c4 + 3][r] = vb.w;
        }
        __syncthreads();
#pragma unroll
        for (int kk = 0; kk < 16; kk++) {
            float4 a0 = *(const float4*)&As[kk][ty * 8];
            float4 a1 = *(const float4*)&As[kk][ty * 8 + 4];
            float4 b0 = *(const float4*)&Bs[kk][tx * 8];
            float4 b1 = *(const float4*)&Bs[kk][tx * 8 + 4];
            float ra[8] = {a0.x, a0.y, a0.z, a0.w, a1.x, a1.y, a1.z, a1.w};
            float rb[8] = {b0.x, b0.y, b0.z, b0.w, b1.x, b1.y, b1.z, b1.w};
#pragma unroll
            for (int i = 0; i < 8; i++)
#pragma unroll
                for (int j = 0; j < 8; j++)
                    acc[i][j] = fmaf(ra[i], rb[j], acc[i][j]);
        }
        __syncthreads();
    }

    float* Eb = d_E + (long)b * LS;
    const int gi0 = row0 + ty * 8, gj0 = col0 + tx * 8;
#pragma unroll
    for (int i = 0; i < 8; i++) {
        int gi = gi0 + i;
        if (gi >= LDIM) break;
#pragma unroll
        for (int h = 0; h < 2; h++) {
            int gj = gj0 + h * 4;
            if (gj < SDIM) {  // SDIM%4==0 -> float4 guard exact
                float4 o;
                o.x = expf(acc[i][h * 4 + 0] * INV_SCALE);
                o.y = expf(acc[i][h * 4 + 1] * INV_SCALE);
                o.z = expf(acc[i][h * 4 + 2] * INV_SCALE);
                o.w = expf(acc[i][h * 4 + 3] * INV_SCALE);
                *(float4*)(Eb + (long)gi * SDIM + gj) = o;
            }
        }
    }
}

// ---- K2a: row sums -> rinv.  grid (LDIM, BATCH), 256 thr ----
__global__ void rowsum_kernel() {
    __shared__ float red[8];
    const int b = blockIdx.y, i = blockIdx.x;
    const float4* r4 = (const float4*)(d_E + (long)b * LS + (long)i * SDIM);
    float s = 0.0f;
    for (int f = threadIdx.x; f < 900; f += 256) {
        float4 v = r4[f];
        s += (v.x + v.y) + (v.z + v.w);
    }
    s = blockSum256(s, red);
    if (threadIdx.x == 0) d_rinv[b * LDIM + i] = 1.0f / s;
}

// ---- K2b: column sums, two-stage deterministic ----
__global__ void colsum_part_kernel() {  // grid (15, CGROUPS, BATCH)
    const int b = blockIdx.z, g = blockIdx.y;
    const int j = blockIdx.x * 256 + threadIdx.x;
    if (j >= SDIM) return;
    const float* p = d_E + (long)b * LS + (long)(g * 225) * SDIM + j;
    float s = 0.0f;
#pragma unroll 5
    for (int ii = 0; ii < 225; ii++) s += p[(long)ii * SDIM];
    d_colpart[(b * CGROUPS + g) * SDIM + j] = s;
}
__global__ void colsum_reduce_kernel() {  // grid 29
    int idx = blockIdx.x * 256 + threadIdx.x;
    if (idx >= BATCH * SDIM) return;
    int b = idx / SDIM, j = idx - b * SDIM;
    float s = 0.0f;
#pragma unroll
    for (int g = 0; g < CGROUPS; g++) s += d_colpart[(b * CGROUPS + g) * SDIM + j];
    d_cinv[idx] = 1.0f / s;
}

// ---- init: wv = 1, colmax bits = 0 ----
__global__ void init_kernel() {  // grid 29
    int idx = blockIdx.x * 256 + threadIdx.x;
    if (idx < BATCH * NP1) d_wv[idx] = 1.0f;
    if (idx < BATCH * SDIM) d_colmaxb[idx] = 0u;
}

// ---- K3a: cm -> out0 + per-row max bits.  grid (450, BATCH) ----
__global__ void cm_rowmax_kernel(float* __restrict__ out0) {
    __shared__ __align__(16) float s_ci[SDIM];
    const int b = blockIdx.y;
    for (int j = threadIdx.x; j < SDIM; j += 256) s_ci[j] = d_cinv[b * SDIM + j];
    __syncthreads();
    const int warp = threadIdx.x >> 5, lane = threadIdx.x & 31;
    const int i = blockIdx.x * 8 + warp;
    const float ri = d_rinv[b * LDIM + i];
    const float4* E4 = (const float4*)(d_E + (long)b * LS + (long)i * SDIM);
    const float4* C4 = (const float4*)s_ci;
    float4* O4 = (float4*)(out0 + (long)b * LS + (long)i * SDIM);
    float mx = 0.0f;
    for (int f = lane; f < 900; f += 32) {
        float4 e = E4[f], c = C4[f];
        float4 r;
        r.x = cm_val(e.x, ri, c.x); r.y = cm_val(e.y, ri, c.y);
        r.z = cm_val(e.z, ri, c.z); r.w = cm_val(e.w, ri, c.w);
        O4[f] = r;
        mx = fmaxf(mx, fmaxf(fmaxf(r.x, r.y), fmaxf(r.z, r.w)));
    }
    mx = warpMax(mx);
    if (lane == 0) d_rowmaxb[b * LDIM + i] = __float_as_uint(mx);
}

// ---- K3b: per-column max bits (cm>0 -> uint order == float order) ----
__global__ void colmax_kernel() {  // grid (15, CGROUPS, BATCH)
    __shared__ float s_ri[225];
    const int b = blockIdx.z, g = blockIdx.y;
    const int i0 = g * 225;
    if (threadIdx.x < 225) s_ri[threadIdx.x] = d_rinv[b * LDIM + i0 + threadIdx.x];
    __syncthreads();
    const int j = blockIdx.x * 256 + threadIdx.x;
    if (j >= SDIM) return;
    const float cj = d_cinv[b * SDIM + j];
    const float* p = d_E + (long)b * LS + (long)i0 * SDIM + j;
    float mx = 0.0f;
#pragma unroll 5
    for (int ii = 0; ii < 225; ii++)
        mx = fmaxf(mx, cm_val(p[(long)ii * SDIM], s_ri[ii], cj));
    atomicMax(&d_colmaxb[b * SDIM + j], __float_as_uint(mx));
}

// ---- K4: cf = cm * mutual (bit-identical recompute + bit compare) ----
__global__ void cf_kernel(float* __restrict__ out1) {  // grid (450, BATCH)
    __shared__ __align__(16) float s_ci[SDIM];
    __shared__ unsigned s_cb[SDIM];
    const int b = blockIdx.y;
    for (int j = threadIdx.x; j < SDIM; j += 256) {
        s_ci[j] = d_cinv[b * SDIM + j];
        s_cb[j] = d_colmaxb[b * SDIM + j];
    }
    __syncthreads();
    const int warp = threadIdx.x >> 5, lane = threadIdx.x & 31;
    const int i = blockIdx.x * 8 + warp;
    const float ri = d_rinv[b * LDIM + i];
    const unsigned rb = d_rowmaxb[b * LDIM + i];
    const float* Er = d_E + (long)b * LS + (long)i * SDIM;
    float* o = out1 + (long)b * LS + (long)i * SDIM;
    for (int j = lane; j < SDIM; j += 32) {
        float cm = cm_val(Er[j], ri, s_ci[j]);
        unsigned cb = __float_as_uint(cm);
        o[j] = (cb == rb && cb == s_cb[j]) ? cm : 0.0f;
    }
}

// ---- Sinkhorn A: wu = mu / (E@wv + A*wv_n); row m analytic ----
__global__ void sinkA_kernel(const float* __restrict__ alphap) {  // grid (451, BATCH)
    const int b = blockIdx.y, tid = threadIdx.x;
    const float A = expf(alphap[0]);
    if (blockIdx.x == 450) {
        __shared__ float red[8];
        float s = 0.0f;
        for (int j = tid; j < NP1; j += 256) s += d_wv[b * NP1 + j];
        s = blockSum256(s, red);
        if (tid == 0) d_wu[b * NP1 + LDIM] = 0.5f / (A * s);
        return;
    }
    __shared__ __align__(16) float swv[SDIM];
    for (int j = tid; j < SDIM; j += 256) swv[j] = d_wv[b * NP1 + j];
    const float wvn = d_wv[b * NP1 + SDIM];
    __syncthreads();
    const int warp = tid >> 5, lane = tid & 31;
    const int i = blockIdx.x * 8 + warp;
    const float4* E4 = (const float4*)(d_E + (long)b * LS + (long)i * SDIM);
    const float4* W4 = (const float4*)swv;
    float a0 = 0.f, a1 = 0.f, a2 = 0.f, a3 = 0.f;
#pragma unroll 4
    for (int f = lane; f < 900; f += 32) {
        float4 e = E4[f], w = W4[f];
        a0 = fmaf(e.x, w.x, a0); a1 = fmaf(e.y, w.y, a1);
        a2 = fmaf(e.z, w.z, a2); a3 = fmaf(e.w, w.w, a3);
    }
    float s = warpSum((a0 + a1) + (a2 + a3));
    if (lane == 0) d_wu[b * NP1 + i] = MU_CONST / (s + A * wvn);
}

// ---- Sinkhorn B1: per-group partials of E^T @ wu.  grid (15, NGROUPS, BATCH) ----
__global__ void sinkB1_kernel() {
    __shared__ float swu[144];
    const int b = blockIdx.z, i0 = blockIdx.y * 144, tid = threadIdx.x;
    if (tid < 144) swu[tid] = d_wu[b * NP1 + i0 + tid];
    __syncthreads();
    const int j = blockIdx.x * 256 + tid;
    if (j >= SDIM) return;
    const float* p = d_E + (long)b * LS + (long)i0 * SDIM + j;
    float a0 = 0.f, a1 = 0.f;
#pragma unroll 8
    for (int ii = 0; ii < 144; ii += 2) {
        a0 = fmaf(p[(long)ii * SDIM], swu[ii], a0);
        a1 = fmaf(p[(long)(ii + 1) * SDIM], swu[ii + 1], a1);
    }
    d_svpart[(b * NGROUPS + blockIdx.y) * NP1 + j] = a0 + a1;
}

// ---- Sinkhorn B2: reduce partials -> wv; blocks 0..28 cols, block 29 wv_n ----
__global__ void sinkB2_kernel(const float* __restrict__ alphap) {  // grid 30
    const float A = expf(alphap[0]);
    if (blockIdx.x == 29) {
        const int lane = threadIdx.x & 31, w = threadIdx.x >> 5;
        if (w < BATCH) {
            float s = 0.0f;
            for (int i = lane; i < NP1; i += 32) s += d_wu[w * NP1 + i];
            s = warpSum(s);
            if (lane == 0) d_wv[w * NP1 + SDIM] = 0.5f / (A * s);
        }
        return;
    }
    int idx = blockIdx.x * 256 + threadIdx.x;
    if (idx >= BATCH * SDIM) return;
    int b = idx / SDIM, j = idx - b * SDIM;
    float s = 0.0f;
#pragma unroll
    for (int g = 0; g < NGROUPS; g++) s += d_svpart[(b * NGROUPS + g) * NP1 + j];
    d_wv[b * NP1 + j] = MU_CONST / (s + A * d_wu[b * NP1 + LDIM]);
}

// ---- Final: out2 = E * wu_i * wv_j * 7200.  grid (450, BATCH) ----
__global__ void final_kernel(float* __restrict__ out2) {
    __shared__ __align__(16) float swv[SDIM];
    const int b = blockIdx.y;
    for (int j = threadIdx.x; j < SDIM; j += 256) swv[j] = d_wv[b * NP1 + j];
    __syncthreads();
    const int warp = threadIdx.x >> 5, lane = threadIdx.x & 31;
    const int i = blockIdx.x * 8 + warp;
    const float wu7200 = d_wu[b * NP1 + i] * 7200.0f;
    const float4* E4 = (const float4*)(d_E + (long)b * LS + (long)i * SDIM);
    const float4* W4 = (const float4*)swv;
    float4* O4 = (float4*)(out2 + (long)b * LS + (long)i * SDIM);
    for (int f = lane; f < 900; f += 32) {
        float4 e = E4[f], w = W4[f];
        float4 o;
        o.x = e.x * wu7200 * w.x; o.y = e.y * wu7200 * w.y;
        o.z = e.z * wu7200 * w.z; o.w = e.w * wu7200 * w.w;
        O4[f] = o;
    }
}

extern "C" void kernel_launch(void* const* d_in, const int* in_sizes, int n_in,
                              void* d_out, int out_size) {
    const float* Q = (const float*)d_in[0];
    const float* R = (const float*)d_in[1];
    const float* alpha = (const float*)d_in[2];
    float* out0 = (float*)d_out;
    float* out1 = out0 + (long)BATCH * LS;
    float* out2 = out1 + (long)BATCH * LS;

    gemm_exp_kernel<<<dim3(29, 29, BATCH), 256>>>(Q, R);
    rowsum_kernel<<<dim3(LDIM, BATCH), 256>>>();
    colsum_part_kernel<<<dim3(15, CGROUPS, BATCH), 256>>>();
    colsum_reduce_kernel<<<29, 256>>>();
    init_kernel<<<29, 256>>>();
    cm_rowmax_kernel<<<dim3(450, BATCH), 256>>>(out0);
    colmax_kernel<<<dim3(15, CGROUPS, BATCH), 256>>>();
    cf_kernel<<<dim3(450, BATCH), 256>>>(out1);

    for (int it = 0; it < 50; it++) {
        sinkA_kernel<<<dim3(451, BATCH), 256>>>(alpha);
        sinkB1_kernel<<<dim3(15, NGROUPS, BATCH), 256>>>();
        sinkB2_kernel<<<30, 256>>>(alpha);
    }
    final_kernel<<<dim3(450, BATCH), 256>>>(out2);
}